// round 16
// baseline (speedup 1.0000x reference)
#include <cuda_runtime.h>
#include <cuda_fp16.h>
#include <math.h>

#define NMAX    100000
#define EMAX    1600000
#define NTYPES  17
#define DIM     128
#define GMAX    64
#define NCHUNK  512      // >= ceil(NMAX/256) = 391
#define NBLK    592      // 148 SMs x 4 resident blocks (guaranteed by launch_bounds)

// ---------------- static scratch (all zero-init; self-restoring across replays) ----------------
__device__ int      g_cnt[NMAX];      // hist fills; scatter drains back to 0
__device__ int      g_rowptr[NMAX];   // chunk-local exclusive; + g_bs[i>>8] on use
__device__ int      g_bs[NCHUNK];     // per-256-chunk totals -> exclusive offsets
__device__ int      g_bar_cnt;        // grid barrier arrive counter (self-resets)
__device__ volatile int g_bar_gen;    // grid barrier generation (monotonic)
__device__ unsigned g_ndp[NMAX];      // (dinv bits & ~31) | type
__device__ int2     g_edge[EMAX];     // {src, (dinv_src bits & ~31) | type_src}
__device__ float    g_htab[NTYPES * DIM];
__device__ uint2    g_y1h[(size_t)NMAX * 32];  // fp16x4/lane: y1s = dinv*relu(conv1)
__device__ float    g_pool[GMAX * DIM];        // final phase re-zeros
__device__ int      g_gcnt[GMAX];              // final phase re-zeros

// ---------------- grid-wide barrier (all NBLK blocks resident) ----------------
__device__ __forceinline__ void gsync() {
    __syncthreads();
    if (threadIdx.x == 0) {
        __threadfence();
        int gen = g_bar_gen;                    // snapshot BEFORE arriving
        if (atomicAdd(&g_bar_cnt, 1) == (int)gridDim.x - 1) {
            g_bar_cnt = 0;
            __threadfence();
            g_bar_gen = gen + 1;                // release
        } else {
            while (g_bar_gen == gen) __nanosleep(64);
            __threadfence();
        }
    }
    __syncthreads();
}

__device__ __forceinline__ void acc_row(float4& acc, uint2 u) {
    float2 f0 = __half22float2(*(__half2*)&u.x);
    float2 f1 = __half22float2(*(__half2*)&u.y);
    acc.x += f0.x; acc.y += f0.y; acc.z += f1.x; acc.w += f1.y;
}

// ---------------- the persistent mega-kernel ----------------
__global__ void __launch_bounds__(256, 4) k_mega(
    const int* __restrict__ node_ids, const int* __restrict__ ei,
    const int* __restrict__ batch,
    const float* __restrict__ emb, const float* __restrict__ W1,
    const float* __restrict__ b1,
    const float* __restrict__ W2, const float* __restrict__ b2,
    float* __restrict__ out, int n, int E, int G)
{
    __shared__ int   wsum[32];
    __shared__ int   s_tot;
    __shared__ uint2 sh2[NTYPES * 32];
    __shared__ uint2 sb2[32];
    __shared__ float warpc[8][8][33];
    __shared__ __align__(16) float sy[8 * DIM];   // float4-accessed: force 16B alignment
    __shared__ int   sg[8];
    __shared__ float pf[2][DIM];

    const int t    = threadIdx.x;
    const int lane = t & 31, w = t >> 5;
    const int NT   = gridDim.x * blockDim.x;
    const int gtid = blockIdx.x * blockDim.x + t;
    const int chunks = (n + 255) >> 8;

    // ---- P1: htab = emb @ W1 ; in-degree histogram ----
    for (int idx = gtid; idx < NTYPES * DIM; idx += NT) {
        int tt = idx / DIM, o = idx % DIM;
        float a0 = 0.f, a1 = 0.f, a2 = 0.f, a3 = 0.f;
        #pragma unroll
        for (int d = 0; d < DIM; d += 4) {
            a0 = fmaf(emb[tt * DIM + d + 0], W1[(d + 0) * DIM + o], a0);
            a1 = fmaf(emb[tt * DIM + d + 1], W1[(d + 1) * DIM + o], a1);
            a2 = fmaf(emb[tt * DIM + d + 2], W1[(d + 2) * DIM + o], a2);
            a3 = fmaf(emb[tt * DIM + d + 3], W1[(d + 3) * DIM + o], a3);
        }
        g_htab[idx] = (a0 + a1) + (a2 + a3);
    }
    for (int e = gtid; e < E; e += NT)
        atomicAdd(&g_cnt[ei[E + e]], 1);

    gsync();

    // ---- P2: per-chunk (256) scan of counts; ndp pack ----
    for (int c = blockIdx.x; c < chunks; c += gridDim.x) {
        int i = c * 256 + t;
        int v = (i < n) ? g_cnt[i] : 0;
        if (i < n) {
            float dv = rsqrtf((float)(v + 1));
            g_ndp[i] = (__float_as_uint(dv) & ~31u) | (unsigned)node_ids[i];
        }
        int x = v;
        #pragma unroll
        for (int off = 1; off < 32; off <<= 1) {
            int y = __shfl_up_sync(0xffffffffu, x, off);
            if (lane >= off) x += y;
        }
        if (lane == 31) wsum[w] = x;
        __syncthreads();
        if (w == 0) {
            int y = (lane < 8) ? wsum[lane] : 0;
            #pragma unroll
            for (int off = 1; off < 8; off <<= 1) {
                int z = __shfl_up_sync(0xffffffffu, y, off);
                if (lane >= off) y += z;
            }
            if (lane < 8) wsum[lane] = y;
        }
        __syncthreads();
        int incl = x + (w > 0 ? wsum[w - 1] : 0);
        if (i < n) g_rowptr[i] = incl - v;     // chunk-local exclusive
        if (t == 255) g_bs[c] = incl;          // chunk total
        __syncthreads();
    }

    gsync();

    // ---- P3: block 0 scans chunk totals (exclusive) ----
    if (blockIdx.x == 0) {
        int carry = 0;
        for (int base = 0; base < chunks; base += 256) {
            int idx = base + t;
            int v = (idx < chunks) ? g_bs[idx] : 0;
            int x = v;
            #pragma unroll
            for (int off = 1; off < 32; off <<= 1) {
                int y = __shfl_up_sync(0xffffffffu, x, off);
                if (lane >= off) x += y;
            }
            if (lane == 31) wsum[w] = x;
            __syncthreads();
            if (w == 0) {
                int y = (lane < 8) ? wsum[lane] : 0;
                #pragma unroll
                for (int off = 1; off < 8; off <<= 1) {
                    int z = __shfl_up_sync(0xffffffffu, y, off);
                    if (lane >= off) y += z;
                }
                if (lane < 8) wsum[lane] = y;
            }
            __syncthreads();
            int incl = x + (w > 0 ? wsum[w - 1] : 0);
            if (t == 255) s_tot = incl;
            __syncthreads();
            if (idx < chunks) g_bs[idx] = incl - v + carry;
            carry += s_tot;
            __syncthreads();
        }
    }

    gsync();

    // ---- P4: CSR placement (g_cnt drains to 0) ----
    for (int e = gtid; e < E; e += NT) {
        int s = ei[e];
        int d = ei[E + e];
        int p = atomicAdd(&g_cnt[d], -1) - 1;
        g_edge[g_rowptr[d] + g_bs[d >> 8] + p] = make_int2(s, (int)__ldg(&g_ndp[s]));
    }

    gsync();

    // ---- P5: layer 1 (8 nodes/warp, 4 lanes/node, HFMA2) ----
    for (int i = t; i < NTYPES * 32; i += blockDim.x) {
        float4 hv = ((const float4*)g_htab)[i];
        __half2 h0 = __floats2half2_rn(hv.x, hv.y);
        __half2 h1 = __floats2half2_rn(hv.z, hv.w);
        uint2 u; u.x = *(unsigned*)&h0; u.y = *(unsigned*)&h1;
        sh2[i] = u;
    }
    if (t < 32) {
        float4 bv = ((const float4*)b1)[t];
        __half2 h0 = __floats2half2_rn(bv.x, bv.y);
        __half2 h1 = __floats2half2_rn(bv.z, bv.w);
        uint2 u; u.x = *(unsigned*)&h0; u.y = *(unsigned*)&h1;
        sb2[t] = u;
    }
    __syncthreads();

    int n64 = (n + 63) >> 6;
    for (int ib = blockIdx.x; ib < n64; ib += gridDim.x) {
        int ibase = (ib * 8 + w) * 8;
        if (ibase < n) {
            #pragma unroll
            for (int j = 0; j < 8; j++) warpc[w][j][lane] = 0.f;

            int grp = lane >> 2, sub = lane & 3;
            int rv = E;
            {
                int iq = ibase + lane;
                if (lane < 9 && iq < n) rv = g_rowptr[iq] + g_bs[iq >> 8];
            }
            int ge0 = __shfl_sync(0xffffffffu, rv, grp);
            int ge1 = __shfl_sync(0xffffffffu, rv, grp + 1);

            __syncwarp();
            unsigned mypk = 0;
            if (lane < 8 && ibase + lane < n) {
                mypk = g_ndp[ibase + lane];
                warpc[w][lane][mypk & 31u] += __uint_as_float(mypk & ~31u);
            }
            __syncwarp();

            if (ibase + grp < n) {
                int e = ge0 + sub;
                if (e < ge1) {
                    unsigned pk = (unsigned)__ldg(&g_edge[e].y);
                    for (;;) {
                        int en = e + 4;
                        unsigned pkn = 0;
                        bool more = en < ge1;
                        if (more) pkn = (unsigned)__ldg(&g_edge[en].y);
                        atomicAdd(&warpc[w][grp][pk & 31u], __uint_as_float(pk & ~31u));
                        if (!more) break;
                        pk = pkn;
                        e = en;
                    }
                }
            }
            __syncwarp();

            #pragma unroll
            for (int k = 0; k < 5; k++) {
                int idx = k * 32 + lane;
                if (idx < 8 * NTYPES) {
                    int j = idx / NTYPES, tt = idx - j * NTYPES;
                    float c = warpc[w][j][tt];
                    __half2 hc = __float2half2_rn(c);
                    *(unsigned*)&warpc[w][j][tt] = *(unsigned*)&hc;
                }
            }
            __syncwarp();

            __half2 acc[8][2];
            #pragma unroll
            for (int j = 0; j < 8; j++) {
                acc[j][0] = __float2half2_rn(0.f);
                acc[j][1] = __float2half2_rn(0.f);
            }
            const unsigned* wcrow = (const unsigned*)&warpc[w][0][0];
            #pragma unroll
            for (int tt = 0; tt < NTYPES; tt++) {
                uint2 hu = sh2[tt * 32 + lane];
                __half2 h0 = *(__half2*)&hu.x;
                __half2 h1 = *(__half2*)&hu.y;
                #pragma unroll
                for (int j = 0; j < 8; j++) {
                    unsigned cu = wcrow[j * 33 + tt];
                    __half2 hc = *(__half2*)&cu;
                    acc[j][0] = __hfma2(hc, h0, acc[j][0]);
                    acc[j][1] = __hfma2(hc, h1, acc[j][1]);
                }
            }

            uint2 bu = sb2[lane];
            __half2 bb0 = *(__half2*)&bu.x;
            __half2 bb1 = *(__half2*)&bu.y;
            __half2 zero = __float2half2_rn(0.f);
            #pragma unroll
            for (int j = 0; j < 8; j++) {
                int i = ibase + j;
                if (i >= n) break;
                float dij = __shfl_sync(0xffffffffu, __uint_as_float(mypk & ~31u), j);
                __half2 d2 = __float2half2_rn(dij);
                __half2 r0 = __hmul2(d2, __hmax2(__hfma2(d2, acc[j][0], bb0), zero));
                __half2 r1 = __hmul2(d2, __hmax2(__hfma2(d2, acc[j][1], bb1), zero));
                uint2 u;
                u.x = *(unsigned*)&r0;
                u.y = *(unsigned*)&r1;
                g_y1h[(size_t)i * 32 + lane] = u;
            }
        }
    }

    gsync();

    // ---- P6: layer 2 aggregation (fp16 gather, fp32 accum) + pooling ----
    int n8 = (n + 7) >> 3;
    for (int ib = blockIdx.x; ib < n8; ib += gridDim.x) {
        int i = ib * 8 + w;
        if (i < n) {
            const uint2* y = (const uint2*)g_y1h;
            float di = __uint_as_float(g_ndp[i] & ~31u);
            float4 acc = {0.f, 0.f, 0.f, 0.f};
            acc_row(acc, __ldg(&y[(size_t)i * 32 + lane]));   // self loop

            int e  = g_rowptr[i] + g_bs[i >> 8];
            int e1 = (i + 1 < n) ? (g_rowptr[i + 1] + g_bs[(i + 1) >> 8]) : E;

            for (; e + 8 <= e1; e += 8) {
                int s0 = g_edge[e + 0].x, s1 = g_edge[e + 1].x;
                int s2 = g_edge[e + 2].x, s3 = g_edge[e + 3].x;
                int s4 = g_edge[e + 4].x, s5 = g_edge[e + 5].x;
                int s6 = g_edge[e + 6].x, s7 = g_edge[e + 7].x;
                uint2 u0 = __ldg(&y[(size_t)s0 * 32 + lane]);
                uint2 u1 = __ldg(&y[(size_t)s1 * 32 + lane]);
                uint2 u2 = __ldg(&y[(size_t)s2 * 32 + lane]);
                uint2 u3 = __ldg(&y[(size_t)s3 * 32 + lane]);
                uint2 u4 = __ldg(&y[(size_t)s4 * 32 + lane]);
                uint2 u5 = __ldg(&y[(size_t)s5 * 32 + lane]);
                uint2 u6 = __ldg(&y[(size_t)s6 * 32 + lane]);
                uint2 u7 = __ldg(&y[(size_t)s7 * 32 + lane]);
                acc_row(acc, u0); acc_row(acc, u1); acc_row(acc, u2); acc_row(acc, u3);
                acc_row(acc, u4); acc_row(acc, u5); acc_row(acc, u6); acc_row(acc, u7);
            }
            for (; e < e1; e++)
                acc_row(acc, __ldg(&y[(size_t)g_edge[e].x * 32 + lane]));

            acc.x *= di; acc.y *= di; acc.z *= di; acc.w *= di;
            ((float4*)sy)[w * 32 + lane] = acc;
            if (lane == 0) sg[w] = batch[i];
        } else {
            if (lane == 0) sg[w] = -1;
        }
        __syncthreads();

        if (t < DIM) {
            float run = 0.f; int cg = -1; int cnt = 0;
            #pragma unroll
            for (int r = 0; r < 8; r++) {
                int g = sg[r];
                if (g < 0) continue;
                if (g != cg) {
                    if (cg >= 0) {
                        atomicAdd(&g_pool[cg * DIM + t], run);
                        if (t == 0) atomicAdd(&g_gcnt[cg], cnt);
                    }
                    cg = g; run = 0.f; cnt = 0;
                }
                run += sy[r * DIM + t];
                cnt++;
            }
            if (cg >= 0) {
                atomicAdd(&g_pool[cg * DIM + t], run);
                if (t == 0) atomicAdd(&g_gcnt[cg], cnt);
            }
        }
        __syncthreads();   // sy/sg reuse next iteration
    }

    gsync();

    // ---- P7: final — out[g] = (pool[g]/cnt[g]) @ W2 + b2 ; re-zero pool/gcnt ----
    {
        int g = blockIdx.x * 2 + (t >> 7);
        int o = t & 127;
        int cval = 0;
        if (g < G) {
            cval = g_gcnt[g];                       // save BEFORE zeroing
            float inv = (cval > 0) ? (1.0f / (float)cval) : 0.f;
            pf[t >> 7][o] = g_pool[g * DIM + o] * inv;
            g_pool[g * DIM + o] = 0.f;
            if (o == 0) g_gcnt[g] = 0;
        }
        __syncthreads();
        if (g < G) {
            const float* p = pf[t >> 7];
            float a0 = 0.f, a1 = 0.f, a2 = 0.f, a3 = 0.f;
            #pragma unroll
            for (int d = 0; d < DIM; d += 4) {
                a0 = fmaf(p[d + 0], W2[(d + 0) * DIM + o], a0);
                a1 = fmaf(p[d + 1], W2[(d + 1) * DIM + o], a1);
                a2 = fmaf(p[d + 2], W2[(d + 2) * DIM + o], a2);
                a3 = fmaf(p[d + 3], W2[(d + 3) * DIM + o], a3);
            }
            out[g * DIM + o] = (cval > 0) ? ((a0 + a1) + (a2 + a3) + b2[o]) : 0.f;
        }
    }
}

// ---------------- launcher ----------------
extern "C" void kernel_launch(void* const* d_in, const int* in_sizes, int n_in,
                              void* d_out, int out_size) {
    const int* node_ids = (const int*)d_in[0];
    const int* ei       = (const int*)d_in[1];
    const int* batch    = (const int*)d_in[2];
    int base = (n_in >= 9 && in_sizes[3] == 1) ? 4 : 3;
    const float* emb = (const float*)d_in[base + 0];
    const float* W1  = (const float*)d_in[base + 1];
    const float* b1  = (const float*)d_in[base + 2];
    const float* W2  = (const float*)d_in[base + 3];
    const float* b2  = (const float*)d_in[base + 4];

    int N = in_sizes[0];
    int E = in_sizes[1] / 2;
    int G = out_size / DIM;

    k_mega<<<NBLK, 256>>>(node_ids, ei, batch, emb, W1, b1, W2, b2,
                          (float*)d_out, N, E, G);
}

// round 17
// speedup vs baseline: 1.4086x; 1.4086x over previous
#include <cuda_runtime.h>
#include <cuda_fp16.h>
#include <math.h>

#define NMAX    100000
#define EMAX    1600000
#define NTYPES  17
#define DIM     128
#define GMAX    64
#define NBMAX   128
#define HTB     9      // htab helper blocks inside k_hist

// ---------------- static scratch (all zero-init; self-restoring across replays) ----------------
__device__ int   g_cnt[NMAX];      // hist fills; scatter drains back to 0
__device__ int   g_rowptr[NMAX];   // local-exclusive; + g_bsums[i>>10] on use
__device__ int   g_bsums[NBMAX];
__device__ int   g_sctr;           // scan election counter (self-resets)
__device__ unsigned g_ndp[NMAX];   // (dinv bits & ~31) | type
__device__ int2  g_edge[EMAX];     // {src, (dinv_src bits & ~31) | type_src}
__device__ float g_htab[NTYPES * DIM];
__device__ uint2 g_y1h[(size_t)NMAX * 32];   // fp16x4/lane: y1s = dinv*relu(conv1)
__device__ float g_pool[GMAX * DIM];         // k_final re-zeros
__device__ int   g_gcnt[GMAX];               // k_final re-zeros

// ---------------- kernels ----------------

// blocks 0..HTB-1: htab = emb @ W1 ; rest: in-degree histogram (2 edges/thread)
__global__ void __launch_bounds__(256) k_hist(const int* __restrict__ ei, int E,
                                              const float* __restrict__ emb,
                                              const float* __restrict__ W1) {
    int b = blockIdx.x;
    if (b < HTB) {
        int idx = b * 256 + threadIdx.x;
        if (idx < NTYPES * DIM) {
            int t = idx / DIM, o = idx % DIM;
            float a0 = 0.f, a1 = 0.f, a2 = 0.f, a3 = 0.f;
            #pragma unroll
            for (int d = 0; d < DIM; d += 4) {
                a0 = fmaf(emb[t * DIM + d + 0], W1[(d + 0) * DIM + o], a0);
                a1 = fmaf(emb[t * DIM + d + 1], W1[(d + 1) * DIM + o], a1);
                a2 = fmaf(emb[t * DIM + d + 2], W1[(d + 2) * DIM + o], a2);
                a3 = fmaf(emb[t * DIM + d + 3], W1[(d + 3) * DIM + o], a3);
            }
            g_htab[idx] = (a0 + a1) + (a2 + a3);
        }
        return;
    }
    int e2 = ((b - HTB) * 256 + threadIdx.x) * 2;
    if (e2 + 1 < E) {
        int2 dd = *(const int2*)&ei[E + e2];
        atomicAdd(&g_cnt[dd.x], 1);
        atomicAdd(&g_cnt[dd.y], 1);
    } else if (e2 < E) {
        atomicAdd(&g_cnt[ei[E + e2]], 1);
    }
}

// per-block scan of counts (warp-shuffle); ndp pack; elected last block scans bsums
__global__ void k_scan1(const int* __restrict__ node_ids, int n) {
    __shared__ int wsum[32];
    __shared__ int s2[NBMAX];
    __shared__ int s_elect;
    int t = threadIdx.x;
    int lane = t & 31, w = t >> 5;
    int i = blockIdx.x * 1024 + t;
    int v = (i < n) ? g_cnt[i] : 0;
    if (i < n) {
        float dv = rsqrtf((float)(v + 1));
        g_ndp[i] = (__float_as_uint(dv) & ~31u) | (unsigned)node_ids[i];
    }

    int x = v;
    #pragma unroll
    for (int off = 1; off < 32; off <<= 1) {
        int y = __shfl_up_sync(0xffffffffu, x, off);
        if (lane >= off) x += y;
    }
    if (lane == 31) wsum[w] = x;
    __syncthreads();
    if (w == 0) {
        int y = wsum[lane];
        #pragma unroll
        for (int off = 1; off < 32; off <<= 1) {
            int z = __shfl_up_sync(0xffffffffu, y, off);
            if (lane >= off) y += z;
        }
        wsum[lane] = y;
    }
    __syncthreads();
    int incl = x + (w > 0 ? wsum[w - 1] : 0);
    if (i < n) g_rowptr[i] = incl - v;           // local exclusive
    if (t == 1023) g_bsums[blockIdx.x] = incl;   // block total
    __syncthreads();

    if (t == 0) {
        __threadfence();
        int old = atomicAdd(&g_sctr, 1);
        s_elect = (old == (int)gridDim.x - 1);
    }
    __syncthreads();
    if (s_elect) {
        int nb = gridDim.x;
        int v0 = 0;
        if (t < NBMAX) { v0 = (t < nb) ? g_bsums[t] : 0; s2[t] = v0; }
        __syncthreads();
        #pragma unroll
        for (int off = 1; off < NBMAX; off <<= 1) {
            int a = 0;
            if (t < NBMAX && t >= off) a = s2[t - off];
            __syncthreads();
            if (t < NBMAX) s2[t] += a;
            __syncthreads();
        }
        if (t < nb) g_bsums[t] = s2[t] - v0;     // exclusive block offsets
        if (t == 0) g_sctr = 0;                  // self-reset for next replay
    }
}

// CSR placement; g_cnt doubles as cursor (drains to 0)
__global__ void k_scatter(const int* __restrict__ ei, int E) {
    int e = blockIdx.x * blockDim.x + threadIdx.x;
    if (e >= E) return;
    int s = ei[e];
    int d = ei[E + e];
    int p = atomicAdd(&g_cnt[d], -1) - 1;
    g_edge[g_rowptr[d] + g_bsums[d >> 10] + p] = make_int2(s, (int)__ldg(&g_ndp[s]));
}

// Layer 1: 8 nodes/warp, 4 lanes/node, pipelined edge gathers, smem fp32
// coefficient atomics, then HFMA2 accumulate (halved FMA work + registers)
__global__ void __launch_bounds__(256) k_layer1(const float* __restrict__ b1, int n, int E) {
    __shared__ uint2 sh2[NTYPES * 32];    // htab as 2x half2 per lane (4 features)
    __shared__ uint2 sb2[32];             // b1  as 2x half2 per lane
    __shared__ float warpc[8][8][33];     // fp32 coeffs; converted in-place to half2 bits
    for (int i = threadIdx.x; i < NTYPES * 32; i += blockDim.x) {
        float4 hv = ((const float4*)g_htab)[i];
        __half2 h0 = __floats2half2_rn(hv.x, hv.y);
        __half2 h1 = __floats2half2_rn(hv.z, hv.w);
        uint2 u; u.x = *(unsigned*)&h0; u.y = *(unsigned*)&h1;
        sh2[i] = u;
    }
    if (threadIdx.x < 32) {
        float4 bv = ((const float4*)b1)[threadIdx.x];
        __half2 h0 = __floats2half2_rn(bv.x, bv.y);
        __half2 h1 = __floats2half2_rn(bv.z, bv.w);
        uint2 u; u.x = *(unsigned*)&h0; u.y = *(unsigned*)&h1;
        sb2[threadIdx.x] = u;
    }
    __syncthreads();

    int warp = threadIdx.x >> 5, lane = threadIdx.x & 31;
    int ibase = (blockIdx.x * 8 + warp) * 8;
    if (ibase >= n) return;

    #pragma unroll
    for (int j = 0; j < 8; j++) warpc[warp][j][lane] = 0.f;

    int grp = lane >> 2;      // node within warp (0..7)
    int sub = lane & 3;

    // row boundaries: lanes 0..8 fetch, broadcast via shfl
    int rv = E;
    {
        int iq = ibase + lane;
        if (lane < 9 && iq < n) rv = g_rowptr[iq] + g_bsums[iq >> 10];
    }
    int ge0 = __shfl_sync(0xffffffffu, rv, grp);
    int ge1 = __shfl_sync(0xffffffffu, rv, grp + 1);

    // self-loop pre-fold (lanes 0..7 own node j=lane)
    __syncwarp();
    unsigned mypk = 0;
    if (lane < 8 && ibase + lane < n) {
        mypk = g_ndp[ibase + lane];
        warpc[warp][lane][mypk & 31u] += __uint_as_float(mypk & ~31u);
    }
    __syncwarp();

    // pipelined edge loop: 4 lanes per node, one LDG in flight ahead
    if (ibase + grp < n) {
        int e = ge0 + sub;
        if (e < ge1) {
            unsigned pk = (unsigned)__ldg(&g_edge[e].y);
            for (;;) {
                int en = e + 4;
                unsigned pkn = 0;
                bool more = en < ge1;
                if (more) pkn = (unsigned)__ldg(&g_edge[en].y);
                atomicAdd(&warpc[warp][grp][pk & 31u], __uint_as_float(pk & ~31u));
                if (!more) break;
                pk = pkn;
                e = en;
            }
        }
    }
    __syncwarp();

    // convert coefficients in-place: float -> broadcast half2 bits
    #pragma unroll
    for (int k = 0; k < 5; k++) {          // 5*32 >= 8*17
        int idx = k * 32 + lane;
        if (idx < 8 * NTYPES) {
            int j = idx / NTYPES, t = idx - j * NTYPES;
            float c = warpc[warp][j][t];
            __half2 hc = __float2half2_rn(c);
            *(unsigned*)&warpc[warp][j][t] = *(unsigned*)&hc;
        }
    }
    __syncwarp();

    // HFMA2 accumulation: one LDS.64 of h serves 8 nodes
    __half2 acc[8][2];
    #pragma unroll
    for (int j = 0; j < 8; j++) {
        acc[j][0] = __float2half2_rn(0.f);
        acc[j][1] = __float2half2_rn(0.f);
    }
    const unsigned* wcrow = (const unsigned*)&warpc[warp][0][0];
    #pragma unroll
    for (int t = 0; t < NTYPES; t++) {
        uint2 hu = sh2[t * 32 + lane];
        __half2 h0 = *(__half2*)&hu.x;
        __half2 h1 = *(__half2*)&hu.y;
        #pragma unroll
        for (int j = 0; j < 8; j++) {
            unsigned cu = wcrow[j * 33 + t];
            __half2 hc = *(__half2*)&cu;
            acc[j][0] = __hfma2(hc, h0, acc[j][0]);
            acc[j][1] = __hfma2(hc, h1, acc[j][1]);
        }
    }

    uint2 bu = sb2[lane];
    __half2 bb0 = *(__half2*)&bu.x;
    __half2 bb1 = *(__half2*)&bu.y;
    __half2 zero = __float2half2_rn(0.f);
    #pragma unroll
    for (int j = 0; j < 8; j++) {
        int i = ibase + j;
        if (i >= n) break;
        float dij = __shfl_sync(0xffffffffu, __uint_as_float(mypk & ~31u), j);
        __half2 d2 = __float2half2_rn(dij);
        __half2 r0 = __hmul2(d2, __hmax2(__hfma2(d2, acc[j][0], bb0), zero));
        __half2 r1 = __hmul2(d2, __hmax2(__hfma2(d2, acc[j][1], bb1), zero));
        uint2 u;
        u.x = *(unsigned*)&r0;
        u.y = *(unsigned*)&r1;
        g_y1h[(size_t)i * 32 + lane] = u;
    }
}

// fp16 pair accumulate + fp32 flush
__device__ __forceinline__ void hacc(uint2 u, __half2& a0, __half2& a1) {
    a0 = __hadd2(a0, *(__half2*)&u.x);
    a1 = __hadd2(a1, *(__half2*)&u.y);
}
__device__ __forceinline__ void hflush(float4& acc, __half2& a0, __half2& a1) {
    float2 f0 = __half22float2(a0);
    float2 f1 = __half22float2(a1);
    acc.x += f0.x; acc.y += f0.y; acc.z += f1.x; acc.w += f1.y;
    a0 = __float2half2_rn(0.f);
    a1 = __float2half2_rn(0.f);
}

// Layer 2 aggregation (fp16 gather, HADD2 accumulate, fp32 flush/8) + pooling
__global__ void __launch_bounds__(256) k_layer2pool(const int* __restrict__ batch, int n, int E) {
    __shared__ __align__(16) float sy[8 * DIM];
    __shared__ int sg[8];

    int warp = threadIdx.x >> 5, lane = threadIdx.x & 31;
    int i = blockIdx.x * 8 + warp;

    if (i < n) {
        const uint2* y = (const uint2*)g_y1h;
        float di = __uint_as_float(g_ndp[i] & ~31u);
        float4 acc = {0.f, 0.f, 0.f, 0.f};
        __half2 a0 = __float2half2_rn(0.f), a1 = __float2half2_rn(0.f);

        hacc(__ldg(&y[(size_t)i * 32 + lane]), a0, a1);   // self loop

        int e  = g_rowptr[i] + g_bsums[i >> 10];
        int e1 = (i + 1 < n) ? (g_rowptr[i + 1] + g_bsums[(i + 1) >> 10]) : E;

        for (; e + 8 <= e1; e += 8) {
            int s0 = g_edge[e + 0].x, s1 = g_edge[e + 1].x;
            int s2 = g_edge[e + 2].x, s3 = g_edge[e + 3].x;
            int s4 = g_edge[e + 4].x, s5 = g_edge[e + 5].x;
            int s6 = g_edge[e + 6].x, s7 = g_edge[e + 7].x;
            uint2 u0 = __ldg(&y[(size_t)s0 * 32 + lane]);
            uint2 u1 = __ldg(&y[(size_t)s1 * 32 + lane]);
            uint2 u2 = __ldg(&y[(size_t)s2 * 32 + lane]);
            uint2 u3 = __ldg(&y[(size_t)s3 * 32 + lane]);
            uint2 u4 = __ldg(&y[(size_t)s4 * 32 + lane]);
            uint2 u5 = __ldg(&y[(size_t)s5 * 32 + lane]);
            uint2 u6 = __ldg(&y[(size_t)s6 * 32 + lane]);
            uint2 u7 = __ldg(&y[(size_t)s7 * 32 + lane]);
            hacc(u0, a0, a1); hacc(u1, a0, a1); hacc(u2, a0, a1); hacc(u3, a0, a1);
            hacc(u4, a0, a1); hacc(u5, a0, a1); hacc(u6, a0, a1); hacc(u7, a0, a1);
            hflush(acc, a0, a1);
        }
        for (; e < e1; e++)
            hacc(__ldg(&y[(size_t)g_edge[e].x * 32 + lane]), a0, a1);
        hflush(acc, a0, a1);

        acc.x *= di; acc.y *= di; acc.z *= di; acc.w *= di;
        ((float4*)sy)[warp * 32 + lane] = acc;
        if (lane == 0) sg[warp] = batch[i];
    } else {
        if (lane == 0) sg[warp] = -1;
    }
    __syncthreads();

    int f = threadIdx.x;
    if (f < DIM) {
        float run = 0.f; int cg = -1; int cnt = 0;
        #pragma unroll
        for (int r = 0; r < 8; r++) {
            int g = sg[r];
            if (g < 0) continue;
            if (g != cg) {
                if (cg >= 0) {
                    atomicAdd(&g_pool[cg * DIM + f], run);
                    if (f == 0) atomicAdd(&g_gcnt[cg], cnt);
                }
                cg = g; run = 0.f; cnt = 0;
            }
            run += sy[r * DIM + f];
            cnt++;
        }
        if (cg >= 0) {
            atomicAdd(&g_pool[cg * DIM + f], run);
            if (f == 0) atomicAdd(&g_gcnt[cg], cnt);
        }
    }
}

// out[g] = (pool[g]/cnt[g]) @ W2 + b2 ; re-zeros pool/gcnt for next replay
__global__ void k_final(const float* __restrict__ W2, const float* __restrict__ b2,
                        float* __restrict__ out) {
    int g = blockIdx.x, o = threadIdx.x;
    __shared__ float p[DIM];
    int c = g_gcnt[g];
    float inv = (c > 0) ? (1.0f / (float)c) : 0.f;
    p[o] = g_pool[g * DIM + o] * inv;
    g_pool[g * DIM + o] = 0.f;
    if (o == 0) g_gcnt[g] = 0;
    __syncthreads();
    float a0 = 0.f, a1 = 0.f, a2 = 0.f, a3 = 0.f;
    #pragma unroll
    for (int d = 0; d < DIM; d += 4) {
        a0 = fmaf(p[d + 0], W2[(d + 0) * DIM + o], a0);
        a1 = fmaf(p[d + 1], W2[(d + 1) * DIM + o], a1);
        a2 = fmaf(p[d + 2], W2[(d + 2) * DIM + o], a2);
        a3 = fmaf(p[d + 3], W2[(d + 3) * DIM + o], a3);
    }
    out[g * DIM + o] = (c > 0) ? ((a0 + a1) + (a2 + a3) + b2[o]) : 0.f;
}

// ---------------- launcher ----------------
extern "C" void kernel_launch(void* const* d_in, const int* in_sizes, int n_in,
                              void* d_out, int out_size) {
    const int* node_ids = (const int*)d_in[0];
    const int* ei       = (const int*)d_in[1];
    const int* batch    = (const int*)d_in[2];
    int base = (n_in >= 9 && in_sizes[3] == 1) ? 4 : 3;
    const float* emb = (const float*)d_in[base + 0];
    const float* W1  = (const float*)d_in[base + 1];
    const float* b1  = (const float*)d_in[base + 2];
    const float* W2  = (const float*)d_in[base + 3];
    const float* b2  = (const float*)d_in[base + 4];

    int N = in_sizes[0];
    int E = in_sizes[1] / 2;
    int G = out_size / DIM;
    int NB = (N + 1023) / 1024;
    int Epairs = (E + 1) / 2;

    k_hist<<<HTB + (Epairs + 255) / 256, 256>>>(ei, E, emb, W1);
    k_scan1<<<NB, 1024>>>(node_ids, N);
    k_scatter<<<(E + 255) / 256, 256>>>(ei, E);
    k_layer1<<<(N + 63) / 64, 256>>>(b1, N, E);
    k_layer2pool<<<(N + 7) / 8, 256>>>(batch, N, E);
    k_final<<<G, DIM>>>(W2, b2, (float*)d_out);
}